// round 13
// baseline (speedup 1.0000x reference)
#include <cuda_runtime.h>
#include <cstdint>

// Problem dims
#define S_LEN 2048
#define BATCH 128
#define EDIM  128
#define LDIM  128
#define GDIM  512   // 4*LDIM, gate order: f, i, g, o

typedef unsigned long long ull;

// 512 MB scratch for precomputed input projections xg[t][b][512] (bias-folded)
__device__ float g_xg[(size_t)S_LEN * BATCH * GDIM];

// ---------------- packed fp32x2 helpers ----------------
__device__ __forceinline__ ull pack2(float a, float b) {
    ull r;
    asm("mov.b64 %0, {%1, %2};" : "=l"(r) : "f"(a), "f"(b));
    return r;
}
__device__ __forceinline__ float lo32(ull v) {
    float a, b;
    asm("mov.b64 {%0, %1}, %2;" : "=f"(a), "=f"(b) : "l"(v));
    return a;
}
__device__ __forceinline__ float hi32(ull v) {
    float a, b;
    asm("mov.b64 {%0, %1}, %2;" : "=f"(a), "=f"(b) : "l"(v));
    return b;
}
#define FFMA2(acc, a, b) asm("fma.rn.f32x2 %0, %1, %2, %0;" : "+l"(acc) : "l"(a), "l"(b))

// ---------------- cp.async helper ----------------
#define CP_ASYNC16(dst_u32, src_ptr) \
    asm volatile("cp.async.ca.shared.global [%0], [%1], 16;" \
                 :: "r"(dst_u32), "l"(src_ptr))

// ---------------- fast activations via MUFU.TANH ----------------
__device__ __forceinline__ float fast_tanh(float x) {
    float y;
    asm("tanh.approx.f32 %0, %1;" : "=f"(y) : "f"(x));
    return y;
}
__device__ __forceinline__ float fast_sigmoid(float x) {
    return fmaf(0.5f, fast_tanh(0.5f * x), 0.5f);
}

// =====================================================================
// Kernel 1: xg = x @ Wi + (bi + bh) via tf32 mma.sync  (tensor pipe)
// THIS ROUND: warp tile 64x64 (was 64x32) -> A-fragment reuse doubles,
// smem fragment traffic 400KB -> 256KB per CTA, LDS instr 3072 -> 2048.
// 128 threads / 4 warps as 2(m) x 2(n); block tile 128x128; K pipelined
// as 4 chunks of 32 with 2 cp.async stages; occupancy 2 (smem 72KB).
// As [2][128][36], Bs [2][32][136] (conflict-free pads, unchanged).
// =====================================================================
#define KC      32          // k per chunk
#define NCHUNK  4
#define AS_STRIDE 36
#define BS_STRIDE 136
#define AS_FLOATS (128 * AS_STRIDE)       // per stage
#define BS_FLOATS (32 * BS_STRIDE)        // per stage

__global__ __launch_bounds__(128, 2) void xg_gemm_tf32(
    const float* __restrict__ x,
    const float* __restrict__ Wi,
    const float* __restrict__ bi,
    const float* __restrict__ bh)
{
    extern __shared__ float sm[];
    float* As     = sm;                              // [2][128][36]
    float* Bs     = sm + 2 * AS_FLOATS;              // [2][32][136]
    float* bias_s = Bs + 2 * BS_FLOATS;              // [128]

    const int tid = threadIdx.x;
    const int bn  = blockIdx.x;            // 4 N tiles (fastest -> L2 x-share)
    const int bm  = blockIdx.y;            // 2048 M tiles

    const uint32_t As_u = (uint32_t)__cvta_generic_to_shared(As);
    const uint32_t Bs_u = (uint32_t)__cvta_generic_to_shared(Bs);

    const float* xbase  = x  + (size_t)bm * 128 * EDIM;
    const float* wibase = Wi + (size_t)bn * 128;

    // ---- chunk loader: chunk c -> stage s (128 threads) ----
    auto issue_chunk = [&](int c, int s) {
        const int kc0 = c * KC;
        // A: 128 rows x 32 k = 1024 granules(16B); 8 per thread
        #pragma unroll
        for (int i = 0; i < 8; i++) {
            const int g   = tid + 128 * i;
            const int row = g >> 3;
            const int kq  = g & 7;
            const uint32_t d = As_u + (uint32_t)((s * AS_FLOATS) + row * AS_STRIDE + kq * 4) * 4u;
            CP_ASYNC16(d, xbase + (size_t)row * EDIM + kc0 + kq * 4);
        }
        // B: 32 k-rows x 128 n = 1024 granules; 8 per thread
        #pragma unroll
        for (int i = 0; i < 8; i++) {
            const int g    = tid + 128 * i;
            const int krow = g >> 5;
            const int nq   = g & 31;
            const uint32_t d = Bs_u + (uint32_t)((s * BS_FLOATS) + krow * BS_STRIDE + nq * 4) * 4u;
            CP_ASYNC16(d, wibase + (size_t)(kc0 + krow) * GDIM + nq * 4);
        }
        asm volatile("cp.async.commit_group;");
    };

    issue_chunk(0, 0);
    issue_chunk(1, 1);
    bias_s[tid] = bi[bn * 128 + tid] + bh[bn * 128 + tid];

    const int lane = tid & 31;
    const int w    = tid >> 5;             // 0..3
    const int mb   = (w & 1) * 64;         // warp m base
    const int nb   = (w >> 1) * 64;        // warp n base
    const int r    = lane >> 2;            // 0..7
    const int cq   = lane & 3;             // 0..3

    float acc[4][8][4];
    #pragma unroll
    for (int f = 0; f < 4; f++)
        #pragma unroll
        for (int g = 0; g < 8; g++)
            #pragma unroll
            for (int i = 0; i < 4; i++) acc[f][g][i] = 0.f;

    #pragma unroll
    for (int c = 0; c < NCHUNK; c++) {
        if (c < NCHUNK - 1) asm volatile("cp.async.wait_group 1;");
        else                asm volatile("cp.async.wait_group 0;");
        __syncthreads();

        const int s = c & 1;
        const float* Asb = As + s * AS_FLOATS;
        const float* Bsb = Bs + s * BS_FLOATS;

        #pragma unroll
        for (int si = 0; si < 4; si++) {
            const int k0 = 8 * si;
            uint32_t a[4][4];
            #pragma unroll
            for (int f = 0; f < 4; f++) {
                const float* ap = Asb + (mb + f * 16 + r) * AS_STRIDE + k0 + cq;
                a[f][0] = __float_as_uint(ap[0]);
                a[f][1] = __float_as_uint(ap[8 * AS_STRIDE]);
                a[f][2] = __float_as_uint(ap[4]);
                a[f][3] = __float_as_uint(ap[8 * AS_STRIDE + 4]);
            }
            uint32_t b[8][2];
            #pragma unroll
            for (int g = 0; g < 8; g++) {
                const float* bp = Bsb + (k0 + cq) * BS_STRIDE + nb + g * 8 + r;
                b[g][0] = __float_as_uint(bp[0]);
                b[g][1] = __float_as_uint(bp[4 * BS_STRIDE]);
            }
            #pragma unroll
            for (int f = 0; f < 4; f++)
                #pragma unroll
                for (int g = 0; g < 8; g++)
                    asm("mma.sync.aligned.m16n8k8.row.col.f32.tf32.tf32.f32 "
                        "{%0,%1,%2,%3}, {%4,%5,%6,%7}, {%8,%9}, {%0,%1,%2,%3};"
                        : "+f"(acc[f][g][0]), "+f"(acc[f][g][1]),
                          "+f"(acc[f][g][2]), "+f"(acc[f][g][3])
                        : "r"(a[f][0]), "r"(a[f][1]), "r"(a[f][2]), "r"(a[f][3]),
                          "r"(b[g][0]), "r"(b[g][1]));
        }

        if (c < NCHUNK - 2) {
            __syncthreads();               // stage s fully consumed
            issue_chunk(c + 2, s);
        }
    }

    // ---- epilogue: add bias, store float2 pairs ----
    #pragma unroll
    for (int f = 0; f < 4; f++) {
        const int mrow = bm * 128 + mb + f * 16 + r;
        #pragma unroll
        for (int g = 0; g < 8; g++) {
            const int ncol = nb + g * 8 + 2 * cq;
            const float b0 = bias_s[ncol];
            const float b1 = bias_s[ncol + 1];
            float* d0 = g_xg + (size_t)mrow * GDIM + bn * 128 + ncol;
            *(float2*)d0 = make_float2(acc[f][g][0] + b0, acc[f][g][1] + b1);
            float* d1 = d0 + (size_t)8 * GDIM;
            *(float2*)d1 = make_float2(acc[f][g][2] + b0, acc[f][g][3] + b1);
        }
    }
}

// =====================================================================
// Kernel 2: persistent per-batch LSTM recurrence + classifier head.
// (R10 confirmed-best config: 256 threads, 2 cols/thread, smem gate
// exchange, REG_Q=26/SM_Q=6 — 104 Wh rows register-resident. UNCHANGED)
// =====================================================================
#define SM_Q   6    // 6 quads  -> rows 0..23 in smem
#define REG_Q  26   // 26 quads -> rows 24..127 in registers

__global__ __launch_bounds__(256, 1) void lstm_rec(
    const float* __restrict__ Wh,
    const float* __restrict__ Wc,
    const float* __restrict__ bc,
    float* __restrict__ out)
{
    extern __shared__ char smraw[];
    ulonglong2* Ws  = (ulonglong2*)smraw;                    // [SM_Q][512]
    float*  h_s  = (float*)(smraw + SM_Q * 512 * 16);        // [128], 16B aligned
    float2* io_s = (float2*)(h_s + 128);                     // [128] (i, o)

    const int p = threadIdx.x;     // 0..255
    const int b = blockIdx.x;      // batch element
    const int ca = p;              // column a: f (p<128) or i (p>=128)
    const int cb = p + 256;        // column b: g (p<128) or o (p>=128)

    // ---- stage Wh rows 0..(4*SM_Q-1) into smem (k-quad packed per column) ----
    #pragma unroll
    for (int q = 0; q < SM_Q; q++) {
        const int k0 = 4 * q;
        #pragma unroll
        for (int s = 0; s < 2; s++) {
            const int col = p + s * 256;
            ulonglong2 u;
            u.x = pack2(__ldg(&Wh[(k0 + 0) * GDIM + col]), __ldg(&Wh[(k0 + 1) * GDIM + col]));
            u.y = pack2(__ldg(&Wh[(k0 + 2) * GDIM + col]), __ldg(&Wh[(k0 + 3) * GDIM + col]));
            Ws[q * 512 + col] = u;
        }
    }
    // ---- stage remaining Wh rows into registers for both columns ----
    ulonglong2 wra[REG_Q], wrb[REG_Q];
    #pragma unroll
    for (int q = 0; q < REG_Q; q++) {
        const int k0 = 4 * SM_Q + 4 * q;
        wra[q].x = pack2(__ldg(&Wh[(k0 + 0) * GDIM + ca]), __ldg(&Wh[(k0 + 1) * GDIM + ca]));
        wra[q].y = pack2(__ldg(&Wh[(k0 + 2) * GDIM + ca]), __ldg(&Wh[(k0 + 3) * GDIM + ca]));
        wrb[q].x = pack2(__ldg(&Wh[(k0 + 0) * GDIM + cb]), __ldg(&Wh[(k0 + 1) * GDIM + cb]));
        wrb[q].y = pack2(__ldg(&Wh[(k0 + 2) * GDIM + cb]), __ldg(&Wh[(k0 + 3) * GDIM + cb]));
    }

    if (p < 128) h_s[p] = 0.f;
    float c_val = 0.f;
    __syncthreads();

    const float* xga = g_xg + (size_t)b * GDIM + ca;
    const float* xgb = g_xg + (size_t)b * GDIM + cb;
    const size_t stepStride = (size_t)BATCH * GDIM;
    float xga_c = __ldg(xga);
    float xga_n = __ldg(xga + stepStride);
    float xgb_c = __ldg(xgb);
    float xgb_n = __ldg(xgb + stepStride);

    const ulonglong2* h4  = (const ulonglong2*)h_s;
    const ulonglong2* wsa = Ws + ca;
    const ulonglong2* wsb = Ws + cb;

    for (int t = 0; t < S_LEN; t++) {
        // prefetch xg for t+2 (branch-free clamped index)
        const size_t off = (size_t)((t + 2 < S_LEN) ? (t + 2) : (S_LEN - 1)) * stepStride;
        const float xga_p = __ldg(xga + off);
        const float xgb_p = __ldg(xgb + off);

        ull accA0 = 0ULL, accA1 = 0ULL, accB0 = 0ULL, accB1 = 0ULL;
        // rows 0..23 from smem
        #pragma unroll
        for (int q = 0; q < SM_Q; q++) {
            ulonglong2 hv = h4[q];
            ulonglong2 wa = wsa[q * 512];
            ulonglong2 wb = wsb[q * 512];
            FFMA2(accA0, wa.x, hv.x);
            FFMA2(accA1, wa.y, hv.y);
            FFMA2(accB0, wb.x, hv.x);
            FFMA2(accB1, wb.y, hv.y);
        }
        // rows 24..127 from registers
        #pragma unroll
        for (int q = 0; q < REG_Q; q++) {
            ulonglong2 hv = h4[SM_Q + q];
            FFMA2(accA0, wra[q].x, hv.x);
            FFMA2(accA1, wra[q].y, hv.y);
            FFMA2(accB0, wrb[q].x, hv.x);
            FFMA2(accB1, wrb[q].y, hv.y);
        }
        float va = (lo32(accA0) + lo32(accA1)) + (hi32(accA0) + hi32(accA1)) + xga_c;
        float vb = (lo32(accB0) + lo32(accB1)) + (hi32(accB0) + hi32(accB1)) + xgb_c;
        xga_c = xga_n; xga_n = xga_p;
        xgb_c = xgb_n; xgb_n = xgb_p;

        float f_act = 0.f, g_act = 0.f;
        if (p < 128) {
            f_act = fast_sigmoid(va);   // forget gate
            g_act = fast_tanh(vb);      // cell candidate
        } else {
            // (i, o) gates -> exchange via smem
            io_s[p - 128] = make_float2(fast_sigmoid(va), fast_sigmoid(vb));
        }
        __syncthreads();

        if (p < 128) {
            float2 io = io_s[p];
            c_val = fmaf(f_act, c_val, io.x * g_act);
            h_s[p] = io.y * fast_tanh(c_val);
        }
        __syncthreads();
    }

    // ---- classifier head: out[b][n] = h @ Wc + bc ----
    if (p < 2) {
        float s = __ldg(&bc[p]);
        #pragma unroll 8
        for (int l = 0; l < 128; l++) s += h_s[l] * __ldg(&Wc[l * 2 + p]);
        out[b * 2 + p] = s;
    }
}

// =====================================================================
extern "C" void kernel_launch(void* const* d_in, const int* in_sizes, int n_in,
                              void* d_out, int out_size)
{
    const float* x  = (const float*)d_in[0];
    const float* Wi = (const float*)d_in[1];
    const float* bi = (const float*)d_in[2];
    const float* Wh = (const float*)d_in[3];
    const float* bh = (const float*)d_in[4];
    const float* Wc = (const float*)d_in[5];
    const float* bc = (const float*)d_in[6];
    float* out = (float*)d_out;

    const int smemA = (2 * AS_FLOATS + 2 * BS_FLOATS + 128) * (int)sizeof(float); // 72192
    const int smemR = SM_Q * 512 * 16 + 128 * (int)sizeof(float)
                    + 128 * (int)sizeof(float2);                                  // 50688

    cudaFuncSetAttribute(xg_gemm_tf32, cudaFuncAttributeMaxDynamicSharedMemorySize, smemA);
    cudaFuncSetAttribute(lstm_rec,     cudaFuncAttributeMaxDynamicSharedMemorySize, smemR);

    dim3 gridA(GDIM / 128, (S_LEN * BATCH) / 128);   // bn fastest -> x shared in L2
    xg_gemm_tf32<<<gridA, 128, smemA>>>(x, Wi, bi, bh);
    lstm_rec<<<BATCH, 256, smemR>>>(Wh, Wc, bc, out);
}

// round 14
// speedup vs baseline: 1.0027x; 1.0027x over previous
#include <cuda_runtime.h>
#include <cstdint>

// Problem dims
#define S_LEN 2048
#define BATCH 128
#define EDIM  128
#define LDIM  128
#define GDIM  512   // 4*LDIM, gate order: f, i, g, o

typedef unsigned long long ull;

// 512 MB scratch for precomputed input projections xg[t][b][512] (bias-folded)
__device__ float g_xg[(size_t)S_LEN * BATCH * GDIM];

// ---------------- packed fp32x2 helpers ----------------
__device__ __forceinline__ ull pack2(float a, float b) {
    ull r;
    asm("mov.b64 %0, {%1, %2};" : "=l"(r) : "f"(a), "f"(b));
    return r;
}
__device__ __forceinline__ float lo32(ull v) {
    float a, b;
    asm("mov.b64 {%0, %1}, %2;" : "=f"(a), "=f"(b) : "l"(v));
    return a;
}
__device__ __forceinline__ float hi32(ull v) {
    float a, b;
    asm("mov.b64 {%0, %1}, %2;" : "=f"(a), "=f"(b) : "l"(v));
    return b;
}
#define FFMA2(acc, a, b) asm("fma.rn.f32x2 %0, %1, %2, %0;" : "+l"(acc) : "l"(a), "l"(b))

// ---------------- cp.async helper ----------------
#define CP_ASYNC16(dst_u32, src_ptr) \
    asm volatile("cp.async.ca.shared.global [%0], [%1], 16;" \
                 :: "r"(dst_u32), "l"(src_ptr))

// ---------------- fast activations via MUFU.TANH ----------------
__device__ __forceinline__ float fast_tanh(float x) {
    float y;
    asm("tanh.approx.f32 %0, %1;" : "=f"(y) : "f"(x));
    return y;
}
__device__ __forceinline__ float fast_sigmoid(float x) {
    return fmaf(0.5f, fast_tanh(0.5f * x), 0.5f);
}

// =====================================================================
// Kernel 1: xg = x @ Wi + (bi + bh) via tf32 mma.sync  (tensor pipe)
// THIS ROUND: PERSISTENT CTAs. 296 CTAs (2/SM) each loop over ~28 of
// the 8192 tiles (tile = bm*4 + bn, bn fastest -> L2 x-share). The
// cp.async chunk stream continues ACROSS tile boundaries, so the only
// exposed DRAM prologue is the very first one per CTA (was 28 waves).
// Inner config = R12 best: 256 thr, 8 warps 2(m)x4(n), warp tile
// 64x32, K as 4 chunks of 32, 2 smem stages, occupancy 2 (smem 72KB).
// =====================================================================
#define KC      32          // k per chunk
#define AS_STRIDE 36
#define BS_STRIDE 136
#define AS_FLOATS (128 * AS_STRIDE)       // per stage
#define BS_FLOATS (32 * BS_STRIDE)        // per stage
#define G_CTAS  296                       // 2 per SM x 148 SMs
#define TOT_TILES ((S_LEN * BATCH / 128) * (GDIM / 128))   // 8192

__global__ __launch_bounds__(256, 2) void xg_gemm_tf32(
    const float* __restrict__ x,
    const float* __restrict__ Wi,
    const float* __restrict__ bi,
    const float* __restrict__ bh)
{
    extern __shared__ float sm[];
    float* As     = sm;                              // [2][128][36]
    float* Bs     = sm + 2 * AS_FLOATS;              // [2][32][136]
    float* bias_s = Bs + 2 * BS_FLOATS;              // [512]

    const int tid = threadIdx.x;
    const int bid = blockIdx.x;

    const uint32_t As_u = (uint32_t)__cvta_generic_to_shared(As);
    const uint32_t Bs_u = (uint32_t)__cvta_generic_to_shared(Bs);

    // tiles for this CTA: bid, bid+G, bid+2G, ...
    const int nt = (TOT_TILES - bid + G_CTAS - 1) / G_CTAS;
    const int NK = 4 * nt;                 // total chunks to stream

    bias_s[tid]       = bi[tid]       + bh[tid];
    bias_s[tid + 256] = bi[tid + 256] + bh[tid + 256];

    // ---- chunk stream: global chunk gk -> (tile j, chunk c, stage s) ----
    auto issue = [&](int gk) {
        const int j  = gk >> 2;
        const int c  = gk & 3;
        const int s  = gk & 1;
        const int tile = bid + j * G_CTAS;
        const int bm = tile >> 2;
        const int bn = tile & 3;
        const float* xbase  = x  + (size_t)bm * 128 * EDIM;
        const float* wibase = Wi + bn * 128;
        const int kc0 = c * KC;
        // A: 128 rows x 32 k = 1024 granules(16B); 4 per thread
        #pragma unroll
        for (int i = 0; i < 4; i++) {
            const int g   = tid + 256 * i;
            const int row = g >> 3;
            const int kq  = g & 7;
            const uint32_t d = As_u + (uint32_t)((s * AS_FLOATS) + row * AS_STRIDE + kq * 4) * 4u;
            CP_ASYNC16(d, xbase + (size_t)row * EDIM + kc0 + kq * 4);
        }
        // B: 32 k-rows x 128 n = 1024 granules; 4 per thread
        #pragma unroll
        for (int i = 0; i < 4; i++) {
            const int g    = tid + 256 * i;
            const int krow = g >> 5;
            const int nq   = g & 31;
            const uint32_t d = Bs_u + (uint32_t)((s * BS_FLOATS) + krow * BS_STRIDE + nq * 4) * 4u;
            CP_ASYNC16(d, wibase + (size_t)(kc0 + krow) * GDIM + nq * 4);
        }
        asm volatile("cp.async.commit_group;");
    };

    issue(0);
    issue(1);

    const int lane = tid & 31;
    const int w    = tid >> 5;
    const int mb   = (w & 1) * 64;         // warp m base
    const int nb   = (w >> 1) * 32;        // warp n base
    const int r    = lane >> 2;            // 0..7
    const int cq   = lane & 3;             // 0..3

    float acc[4][4][4];
    #pragma unroll
    for (int f = 0; f < 4; f++)
        #pragma unroll
        for (int g = 0; g < 4; g++)
            #pragma unroll
            for (int i = 0; i < 4; i++) acc[f][g][i] = 0.f;

    for (int k = 0; k < NK; k++) {
        if (k <= NK - 2) asm volatile("cp.async.wait_group 1;");
        else             asm volatile("cp.async.wait_group 0;");
        __syncthreads();

        const int s = k & 1;
        const float* Asb = As + s * AS_FLOATS;
        const float* Bsb = Bs + s * BS_FLOATS;

        #pragma unroll
        for (int si = 0; si < 4; si++) {
            const int k0 = 8 * si;
            uint32_t a[4][4];
            #pragma unroll
            for (int f = 0; f < 4; f++) {
                const float* ap = Asb + (mb + f * 16 + r) * AS_STRIDE + k0 + cq;
                a[f][0] = __float_as_uint(ap[0]);
                a[f][1] = __float_as_uint(ap[8 * AS_STRIDE]);
                a[f][2] = __float_as_uint(ap[4]);
                a[f][3] = __float_as_uint(ap[8 * AS_STRIDE + 4]);
            }
            uint32_t b[4][2];
            #pragma unroll
            for (int g = 0; g < 4; g++) {
                const float* bp = Bsb + (k0 + cq) * BS_STRIDE + nb + g * 8 + r;
                b[g][0] = __float_as_uint(bp[0]);
                b[g][1] = __float_as_uint(bp[4 * BS_STRIDE]);
            }
            #pragma unroll
            for (int f = 0; f < 4; f++)
                #pragma unroll
                for (int g = 0; g < 4; g++)
                    asm("mma.sync.aligned.m16n8k8.row.col.f32.tf32.tf32.f32 "
                        "{%0,%1,%2,%3}, {%4,%5,%6,%7}, {%8,%9}, {%0,%1,%2,%3};"
                        : "+f"(acc[f][g][0]), "+f"(acc[f][g][1]),
                          "+f"(acc[f][g][2]), "+f"(acc[f][g][3])
                        : "r"(a[f][0]), "r"(a[f][1]), "r"(a[f][2]), "r"(a[f][3]),
                          "r"(b[g][0]), "r"(b[g][1]));
        }

        // stage consumed -> stream next chunk (possibly next tile's)
        if (k + 2 < NK) {
            __syncthreads();
            issue(k + 2);
        }

        // tile finished -> epilogue while next tile's loads are in flight
        if ((k & 3) == 3) {
            const int tile = bid + (k >> 2) * G_CTAS;
            const int bm = tile >> 2;
            const int bn = tile & 3;
            #pragma unroll
            for (int f = 0; f < 4; f++) {
                const int mrow = bm * 128 + mb + f * 16 + r;
                #pragma unroll
                for (int g = 0; g < 4; g++) {
                    const int ncol = nb + g * 8 + 2 * cq;
                    const float b0 = bias_s[bn * 128 + ncol];
                    const float b1 = bias_s[bn * 128 + ncol + 1];
                    float* d0 = g_xg + (size_t)mrow * GDIM + bn * 128 + ncol;
                    *(float2*)d0 = make_float2(acc[f][g][0] + b0, acc[f][g][1] + b1);
                    float* d1 = d0 + (size_t)8 * GDIM;
                    *(float2*)d1 = make_float2(acc[f][g][2] + b0, acc[f][g][3] + b1);
                    acc[f][g][0] = 0.f; acc[f][g][1] = 0.f;
                    acc[f][g][2] = 0.f; acc[f][g][3] = 0.f;
                }
            }
        }
    }
}

// =====================================================================
// Kernel 2: persistent per-batch LSTM recurrence + classifier head.
// (R10 confirmed-best config: 256 threads, 2 cols/thread, smem gate
// exchange, REG_Q=26/SM_Q=6 — 104 Wh rows register-resident. UNCHANGED)
// =====================================================================
#define SM_Q   6    // 6 quads  -> rows 0..23 in smem
#define REG_Q  26   // 26 quads -> rows 24..127 in registers

__global__ __launch_bounds__(256, 1) void lstm_rec(
    const float* __restrict__ Wh,
    const float* __restrict__ Wc,
    const float* __restrict__ bc,
    float* __restrict__ out)
{
    extern __shared__ char smraw[];
    ulonglong2* Ws  = (ulonglong2*)smraw;                    // [SM_Q][512]
    float*  h_s  = (float*)(smraw + SM_Q * 512 * 16);        // [128], 16B aligned
    float2* io_s = (float2*)(h_s + 128);                     // [128] (i, o)

    const int p = threadIdx.x;     // 0..255
    const int b = blockIdx.x;      // batch element
    const int ca = p;              // column a: f (p<128) or i (p>=128)
    const int cb = p + 256;        // column b: g (p<128) or o (p>=128)

    // ---- stage Wh rows 0..(4*SM_Q-1) into smem (k-quad packed per column) ----
    #pragma unroll
    for (int q = 0; q < SM_Q; q++) {
        const int k0 = 4 * q;
        #pragma unroll
        for (int s = 0; s < 2; s++) {
            const int col = p + s * 256;
            ulonglong2 u;
            u.x = pack2(__ldg(&Wh[(k0 + 0) * GDIM + col]), __ldg(&Wh[(k0 + 1) * GDIM + col]));
            u.y = pack2(__ldg(&Wh[(k0 + 2) * GDIM + col]), __ldg(&Wh[(k0 + 3) * GDIM + col]));
            Ws[q * 512 + col] = u;
        }
    }
    // ---- stage remaining Wh rows into registers for both columns ----
    ulonglong2 wra[REG_Q], wrb[REG_Q];
    #pragma unroll
    for (int q = 0; q < REG_Q; q++) {
        const int k0 = 4 * SM_Q + 4 * q;
        wra[q].x = pack2(__ldg(&Wh[(k0 + 0) * GDIM + ca]), __ldg(&Wh[(k0 + 1) * GDIM + ca]));
        wra[q].y = pack2(__ldg(&Wh[(k0 + 2) * GDIM + ca]), __ldg(&Wh[(k0 + 3) * GDIM + ca]));
        wrb[q].x = pack2(__ldg(&Wh[(k0 + 0) * GDIM + cb]), __ldg(&Wh[(k0 + 1) * GDIM + cb]));
        wrb[q].y = pack2(__ldg(&Wh[(k0 + 2) * GDIM + cb]), __ldg(&Wh[(k0 + 3) * GDIM + cb]));
    }

    if (p < 128) h_s[p] = 0.f;
    float c_val = 0.f;
    __syncthreads();

    const float* xga = g_xg + (size_t)b * GDIM + ca;
    const float* xgb = g_xg + (size_t)b * GDIM + cb;
    const size_t stepStride = (size_t)BATCH * GDIM;
    float xga_c = __ldg(xga);
    float xga_n = __ldg(xga + stepStride);
    float xgb_c = __ldg(xgb);
    float xgb_n = __ldg(xgb + stepStride);

    const ulonglong2* h4  = (const ulonglong2*)h_s;
    const ulonglong2* wsa = Ws + ca;
    const ulonglong2* wsb = Ws + cb;

    for (int t = 0; t < S_LEN; t++) {
        // prefetch xg for t+2 (branch-free clamped index)
        const size_t off = (size_t)((t + 2 < S_LEN) ? (t + 2) : (S_LEN - 1)) * stepStride;
        const float xga_p = __ldg(xga + off);
        const float xgb_p = __ldg(xgb + off);

        ull accA0 = 0ULL, accA1 = 0ULL, accB0 = 0ULL, accB1 = 0ULL;
        // rows 0..23 from smem
        #pragma unroll
        for (int q = 0; q < SM_Q; q++) {
            ulonglong2 hv = h4[q];
            ulonglong2 wa = wsa[q * 512];
            ulonglong2 wb = wsb[q * 512];
            FFMA2(accA0, wa.x, hv.x);
            FFMA2(accA1, wa.y, hv.y);
            FFMA2(accB0, wb.x, hv.x);
            FFMA2(accB1, wb.y, hv.y);
        }
        // rows 24..127 from registers
        #pragma unroll
        for (int q = 0; q < REG_Q; q++) {
            ulonglong2 hv = h4[SM_Q + q];
            FFMA2(accA0, wra[q].x, hv.x);
            FFMA2(accA1, wra[q].y, hv.y);
            FFMA2(accB0, wrb[q].x, hv.x);
            FFMA2(accB1, wrb[q].y, hv.y);
        }
        float va = (lo32(accA0) + lo32(accA1)) + (hi32(accA0) + hi32(accA1)) + xga_c;
        float vb = (lo32(accB0) + lo32(accB1)) + (hi32(accB0) + hi32(accB1)) + xgb_c;
        xga_c = xga_n; xga_n = xga_p;
        xgb_c = xgb_n; xgb_n = xgb_p;

        float f_act = 0.f, g_act = 0.f;
        if (p < 128) {
            f_act = fast_sigmoid(va);   // forget gate
            g_act = fast_tanh(vb);      // cell candidate
        } else {
            // (i, o) gates -> exchange via smem
            io_s[p - 128] = make_float2(fast_sigmoid(va), fast_sigmoid(vb));
        }
        __syncthreads();

        if (p < 128) {
            float2 io = io_s[p];
            c_val = fmaf(f_act, c_val, io.x * g_act);
            h_s[p] = io.y * fast_tanh(c_val);
        }
        __syncthreads();
    }

    // ---- classifier head: out[b][n] = h @ Wc + bc ----
    if (p < 2) {
        float s = __ldg(&bc[p]);
        #pragma unroll 8
        for (int l = 0; l < 128; l++) s += h_s[l] * __ldg(&Wc[l * 2 + p]);
        out[b * 2 + p] = s;
    }
}

// =====================================================================
extern "C" void kernel_launch(void* const* d_in, const int* in_sizes, int n_in,
                              void* d_out, int out_size)
{
    const float* x  = (const float*)d_in[0];
    const float* Wi = (const float*)d_in[1];
    const float* bi = (const float*)d_in[2];
    const float* Wh = (const float*)d_in[3];
    const float* bh = (const float*)d_in[4];
    const float* Wc = (const float*)d_in[5];
    const float* bc = (const float*)d_in[6];
    float* out = (float*)d_out;

    const int smemA = (2 * AS_FLOATS + 2 * BS_FLOATS + 512) * (int)sizeof(float); // 73728
    const int smemR = SM_Q * 512 * 16 + 128 * (int)sizeof(float)
                    + 128 * (int)sizeof(float2);                                  // 50688

    cudaFuncSetAttribute(xg_gemm_tf32, cudaFuncAttributeMaxDynamicSharedMemorySize, smemA);
    cudaFuncSetAttribute(lstm_rec,     cudaFuncAttributeMaxDynamicSharedMemorySize, smemR);

    xg_gemm_tf32<<<G_CTAS, 256, smemA>>>(x, Wi, bi, bh);
    lstm_rec<<<BATCH, 256, smemR>>>(Wh, Wc, bc, out);
}

// round 17
// speedup vs baseline: 1.0414x; 1.0387x over previous
#include <cuda_runtime.h>
#include <cuda_fp16.h>
#include <cstdint>

// Problem dims
#define S_LEN 2048
#define BATCH 128
#define EDIM  128
#define LDIM  128
#define GDIM  512   // 4*LDIM, gate order: f, i, g, o

typedef unsigned long long ull;

// scratch: xg[t][b][512] (bias-folded), x in half, Wi^T in half [n][k]
__device__ float  g_xg[(size_t)S_LEN * BATCH * GDIM];
__device__ __half g_xh[(size_t)S_LEN * BATCH * EDIM];
__device__ __half g_wiTh[GDIM * EDIM];

// ---------------- packed fp32x2 helpers ----------------
__device__ __forceinline__ ull pack2(float a, float b) {
    ull r;
    asm("mov.b64 %0, {%1, %2};" : "=l"(r) : "f"(a), "f"(b));
    return r;
}
__device__ __forceinline__ float lo32(ull v) {
    float a, b;
    asm("mov.b64 {%0, %1}, %2;" : "=f"(a), "=f"(b) : "l"(v));
    return a;
}
__device__ __forceinline__ float hi32(ull v) {
    float a, b;
    asm("mov.b64 {%0, %1}, %2;" : "=f"(a), "=f"(b) : "l"(v));
    return b;
}
#define FFMA2(acc, a, b) asm("fma.rn.f32x2 %0, %1, %2, %0;" : "+l"(acc) : "l"(a), "l"(b))

// ---------------- cp.async ----------------
#define CP_ASYNC16(dst_u32, src_ptr) \
    asm volatile("cp.async.ca.shared.global [%0], [%1], 16;" \
                 :: "r"(dst_u32), "l"(src_ptr))

// ---------------- fast activations via MUFU.TANH ----------------
__device__ __forceinline__ float fast_tanh(float x) {
    float y;
    asm("tanh.approx.f32 %0, %1;" : "=f"(y) : "f"(x));
    return y;
}
__device__ __forceinline__ float fast_sigmoid(float x) {
    return fmaf(0.5f, fast_tanh(0.5f * x), 0.5f);
}

// =====================================================================
// Kernel 0a: x (fp32) -> g_xh (fp16), float4 granularity
// =====================================================================
__global__ __launch_bounds__(256) void x_to_half(const float* __restrict__ x) {
    const size_t g = (size_t)blockIdx.x * 256 + threadIdx.x;  // 8.39M threads
    float4 v = ((const float4*)x)[g];
    __half2 h0 = __floats2half2_rn(v.x, v.y);
    __half2 h1 = __floats2half2_rn(v.z, v.w);
    uint2 u;
    u.x = *(uint32_t*)&h0;
    u.y = *(uint32_t*)&h1;
    ((uint2*)g_xh)[g] = u;
}

// =====================================================================
// Kernel 0b: Wi [k=128][n=512] fp32 -> g_wiTh [n=512][k=128] fp16
// =====================================================================
__global__ __launch_bounds__(256) void wi_to_half_T(const float* __restrict__ Wi) {
    const int g = blockIdx.x * 256 + threadIdx.x;  // 0..65535
    const int n = g >> 7;        // 0..511
    const int k = g & 127;       // 0..127
    g_wiTh[g] = __float2half_rn(Wi[k * GDIM + n]);
}

// =====================================================================
// Kernel 1: xg = x @ Wi + (bi + bh) via fp16 mma.sync.m16n8k16
// (legacy tensor path, 2x MACs/instr vs tf32 m16n8k8 at same issue rate)
// R12-proven skeleton: block tile 128x128, 256 thr, 8 warps 2(m)x4(n),
// warp tile 64x32, K as 4 chunks of 32 through 2 cp.async smem stages,
// occupancy 2. Stages: A/B [128 rows][40 halves] (80B rows, pad ->
// conflict-free: r*80 mod 128 distinct per 16B, cq*4 fills within).
// =====================================================================
#define KC      32          // k halves per chunk
#define ROW_H   40          // halves per smem row (64B data + 16B pad)
#define STAGE_H (128 * ROW_H)             // halves per stage (A or B)
#define STAGE_B (STAGE_H * 2)             // bytes per stage = 10240

__global__ __launch_bounds__(256, 2) void xg_gemm_fp16(
    const float* __restrict__ bi,
    const float* __restrict__ bh)
{
    extern __shared__ char smraw[];
    __half* As     = (__half*)smraw;                         // [2][128][40]
    __half* Bs     = (__half*)(smraw + 2 * STAGE_B);         // [2][128][40]
    float*  bias_s = (float*)(smraw + 4 * STAGE_B);          // [128]

    const int tid = threadIdx.x;
    const int bn  = blockIdx.x;            // 4 N tiles (fastest -> L2 x-share)
    const int bm  = blockIdx.y;            // 2048 M tiles

    const uint32_t As_u = (uint32_t)__cvta_generic_to_shared(As);
    const uint32_t Bs_u = (uint32_t)__cvta_generic_to_shared(Bs);

    const __half* xbase = g_xh + (size_t)bm * 128 * EDIM;
    const __half* wbase = g_wiTh + (size_t)bn * 128 * EDIM;

    // ---- chunk loader: chunk c -> stage s ----
    auto issue_chunk = [&](int c, int s) {
        const int kc0 = c * KC;            // half offset in k
        // A: 128 rows x 4 granules(16B=8 halves) = 512; 2 per thread
        #pragma unroll
        for (int i = 0; i < 2; i++) {
            const int g   = tid + 256 * i;
            const int row = g >> 2;
            const int kq  = g & 3;
            const uint32_t d = As_u + (uint32_t)(s * STAGE_B + row * (ROW_H * 2) + kq * 16);
            CP_ASYNC16(d, xbase + (size_t)row * EDIM + kc0 + kq * 8);
        }
        // B: 128 n-rows x 4 granules = 512; 2 per thread
        #pragma unroll
        for (int i = 0; i < 2; i++) {
            const int g   = tid + 256 * i;
            const int row = g >> 2;
            const int kq  = g & 3;
            const uint32_t d = Bs_u + (uint32_t)(s * STAGE_B + row * (ROW_H * 2) + kq * 16);
            CP_ASYNC16(d, wbase + (size_t)row * EDIM + kc0 + kq * 8);
        }
        asm volatile("cp.async.commit_group;");
    };

    issue_chunk(0, 0);
    issue_chunk(1, 1);
    if (tid < 128) bias_s[tid] = bi[bn * 128 + tid] + bh[bn * 128 + tid];

    const int lane = tid & 31;
    const int w    = tid >> 5;
    const int mb   = (w & 1) * 64;         // warp m base
    const int nb   = (w >> 1) * 32;        // warp n base
    const int r    = lane >> 2;            // 0..7
    const int cq   = lane & 3;             // 0..3

    float acc[4][4][4];
    #pragma unroll
    for (int f = 0; f < 4; f++)
        #pragma unroll
        for (int g = 0; g < 4; g++)
            #pragma unroll
            for (int i = 0; i < 4; i++) acc[f][g][i] = 0.f;

    #pragma unroll
    for (int c = 0; c < 4; c++) {
        if (c < 3) asm volatile("cp.async.wait_group 1;");
        else       asm volatile("cp.async.wait_group 0;");
        __syncthreads();

        const int s = c & 1;
        const __half* Asb = As + s * STAGE_H;
        const __half* Bsb = Bs + s * STAGE_H;

        #pragma unroll
        for (int ks = 0; ks < 2; ks++) {   // 2 k16-steps per 32-k chunk
            const int k0 = ks * 16;        // half offset
            uint32_t a[4][4];
            #pragma unroll
            for (int f = 0; f < 4; f++) {
                const __half* ap = Asb + (mb + f * 16 + r) * ROW_H + k0 + 2 * cq;
                a[f][0] = *(const uint32_t*)(ap);                 // row r,   k 2cq..+1
                a[f][1] = *(const uint32_t*)(ap + 8 * ROW_H);     // row r+8
                a[f][2] = *(const uint32_t*)(ap + 8);             // row r,   k 8+2cq
                a[f][3] = *(const uint32_t*)(ap + 8 * ROW_H + 8); // row r+8
            }
            uint32_t b[4][2];
            #pragma unroll
            for (int g = 0; g < 4; g++) {
                const __half* bp = Bsb + (nb + g * 8 + r) * ROW_H + k0 + 2 * cq;
                b[g][0] = *(const uint32_t*)(bp);                 // col, k 2cq..+1
                b[g][1] = *(const uint32_t*)(bp + 8);             // col, k 8+2cq
            }
            #pragma unroll
            for (int f = 0; f < 4; f++)
                #pragma unroll
                for (int g = 0; g < 4; g++)
                    asm("mma.sync.aligned.m16n8k16.row.col.f32.f16.f16.f32 "
                        "{%0,%1,%2,%3}, {%4,%5,%6,%7}, {%8,%9}, {%0,%1,%2,%3};"
                        : "+f"(acc[f][g][0]), "+f"(acc[f][g][1]),
                          "+f"(acc[f][g][2]), "+f"(acc[f][g][3])
                        : "r"(a[f][0]), "r"(a[f][1]), "r"(a[f][2]), "r"(a[f][3]),
                          "r"(b[g][0]), "r"(b[g][1]));
        }

        if (c < 2) {
            __syncthreads();               // stage s fully consumed
            issue_chunk(c + 2, s);
        }
    }

    // ---- epilogue: add bias, store float2 pairs ----
    #pragma unroll
    for (int f = 0; f < 4; f++) {
        const int mrow = bm * 128 + mb + f * 16 + r;
        #pragma unroll
        for (int g = 0; g < 4; g++) {
            const int ncol = nb + g * 8 + 2 * cq;
            const float b0 = bias_s[ncol];
            const float b1 = bias_s[ncol + 1];
            float* d0 = g_xg + (size_t)mrow * GDIM + bn * 128 + ncol;
            *(float2*)d0 = make_float2(acc[f][g][0] + b0, acc[f][g][1] + b1);
            float* d1 = d0 + (size_t)8 * GDIM;
            *(float2*)d1 = make_float2(acc[f][g][2] + b0, acc[f][g][3] + b1);
        }
    }
}

// =====================================================================
// Kernel 2: persistent per-batch LSTM recurrence + classifier head.
// (R10 confirmed-best config: 256 threads, 2 cols/thread, smem gate
// exchange, REG_Q=26/SM_Q=6 — 104 Wh rows register-resident. UNCHANGED)
// =====================================================================
#define SM_Q   6    // 6 quads  -> rows 0..23 in smem
#define REG_Q  26   // 26 quads -> rows 24..127 in registers

__global__ __launch_bounds__(256, 1) void lstm_rec(
    const float* __restrict__ Wh,
    const float* __restrict__ Wc,
    const float* __restrict__ bc,
    float* __restrict__ out)
{
    extern __shared__ char smraw[];
    ulonglong2* Ws  = (ulonglong2*)smraw;                    // [SM_Q][512]
    float*  h_s  = (float*)(smraw + SM_Q * 512 * 16);        // [128], 16B aligned
    float2* io_s = (float2*)(h_s + 128);                     // [128] (i, o)

    const int p = threadIdx.x;     // 0..255
    const int b = blockIdx.x;      // batch element
    const int ca = p;              // column a: f (p<128) or i (p>=128)
    const int cb = p + 256;        // column b: g (p<128) or o (p>=128)

    #pragma unroll
    for (int q = 0; q < SM_Q; q++) {
        const int k0 = 4 * q;
        #pragma unroll
        for (int s = 0; s < 2; s++) {
            const int col = p + s * 256;
            ulonglong2 u;
            u.x = pack2(__ldg(&Wh[(k0 + 0) * GDIM + col]), __ldg(&Wh[(k0 + 1) * GDIM + col]));
            u.y = pack2(__ldg(&Wh[(k0 + 2) * GDIM + col]), __ldg(&Wh[(k0 + 3) * GDIM + col]));
            Ws[q * 512 + col] = u;
        }
    }
    ulonglong2 wra[REG_Q], wrb[REG_Q];
    #pragma unroll
    for (int q = 0; q < REG_Q; q++) {
        const int k0 = 4 * SM_Q + 4 * q;
        wra[q].x = pack2(__ldg(&Wh[(k0 + 0) * GDIM + ca]), __ldg(&Wh[(k0 + 1) * GDIM + ca]));
        wra[q].y = pack2(__ldg(&Wh[(k0 + 2) * GDIM + ca]), __ldg(&Wh[(k0 + 3) * GDIM + ca]));
        wrb[q].x = pack2(__ldg(&Wh[(k0 + 0) * GDIM + cb]), __ldg(&Wh[(k0 + 1) * GDIM + cb]));
        wrb[q].y = pack2(__ldg(&Wh[(k0 + 2) * GDIM + cb]), __ldg(&Wh[(k0 + 3) * GDIM + cb]));
    }

    if (p < 128) h_s[p] = 0.f;
    float c_val = 0.f;
    __syncthreads();

    const float* xga = g_xg + (size_t)b * GDIM + ca;
    const float* xgb = g_xg + (size_t)b * GDIM + cb;
    const size_t stepStride = (size_t)BATCH * GDIM;
    float xga_c = __ldg(xga);
    float xga_n = __ldg(xga + stepStride);
    float xgb_c = __ldg(xgb);
    float xgb_n = __ldg(xgb + stepStride);

    const ulonglong2* h4  = (const ulonglong2*)h_s;
    const ulonglong2* wsa = Ws + ca;
    const ulonglong2* wsb = Ws + cb;

    for (int t = 0; t < S_LEN; t++) {
        const size_t off = (size_t)((t + 2 < S_LEN) ? (t + 2) : (S_LEN - 1)) * stepStride;
        const float xga_p = __ldg(xga + off);
        const float xgb_p = __ldg(xgb + off);

        ull accA0 = 0ULL, accA1 = 0ULL, accB0 = 0ULL, accB1 = 0ULL;
        #pragma unroll
        for (int q = 0; q < SM_Q; q++) {
            ulonglong2 hv = h4[q];
            ulonglong2 wa = wsa[q * 512];
            ulonglong2 wb = wsb[q * 512];
            FFMA2(accA0, wa.x, hv.x);
            FFMA2(accA1, wa.y, hv.y);
            FFMA2(accB0, wb.x, hv.x);
            FFMA2(accB1, wb.y, hv.y);
        }
        #pragma unroll
        for (int q = 0; q < REG_Q; q++) {
            ulonglong2 hv = h4[SM_Q + q];
            FFMA2(accA0, wra[q].x, hv.x);
            FFMA2(accA1, wra[q].y, hv.y);
            FFMA2(accB0, wrb[q].x, hv.x);
            FFMA2(accB1, wrb[q].y, hv.y);
        }
        float va = (lo32(accA0) + lo32(accA1)) + (hi32(accA0) + hi32(accA1)) + xga_c;
        float vb = (lo32(accB0) + lo32(accB1)) + (hi32(accB0) + hi32(accB1)) + xgb_c;
        xga_c = xga_n; xga_n = xga_p;
        xgb_c = xgb_n; xgb_n = xgb_p;

        float f_act = 0.f, g_act = 0.f;
        if (p < 128) {
            f_act = fast_sigmoid(va);
            g_act = fast_tanh(vb);
        } else {
            io_s[p - 128] = make_float2(fast_sigmoid(va), fast_sigmoid(vb));
        }
        __syncthreads();

        if (p < 128) {
            float2 io = io_s[p];
            c_val = fmaf(f_act, c_val, io.x * g_act);
            h_s[p] = io.y * fast_tanh(c_val);
        }
        __syncthreads();
    }

    if (p < 2) {
        float s = __ldg(&bc[p]);
        #pragma unroll 8
        for (int l = 0; l < 128; l++) s += h_s[l] * __ldg(&Wc[l * 2 + p]);
        out[b * 2 + p] = s;
    }
}

// =====================================================================
extern "C" void kernel_launch(void* const* d_in, const int* in_sizes, int n_in,
                              void* d_out, int out_size)
{
    const float* x  = (const float*)d_in[0];
    const float* Wi = (const float*)d_in[1];
    const float* bi = (const float*)d_in[2];
    const float* Wh = (const float*)d_in[3];
    const float* bh = (const float*)d_in[4];
    const float* Wc = (const float*)d_in[5];
    const float* bc = (const float*)d_in[6];
    float* out = (float*)d_out;

    const int smemA = 4 * STAGE_B + 128 * (int)sizeof(float);    // 41472
    const int smemR = SM_Q * 512 * 16 + 128 * (int)sizeof(float)
                    + 128 * (int)sizeof(float2);                 // 50688

    cudaFuncSetAttribute(xg_gemm_fp16, cudaFuncAttributeMaxDynamicSharedMemorySize, smemA);
    cudaFuncSetAttribute(lstm_rec,     cudaFuncAttributeMaxDynamicSharedMemorySize, smemR);

    // pre-pass conversions
    x_to_half<<<(int)(((size_t)S_LEN * BATCH * EDIM / 4) / 256), 256>>>(x);
    wi_to_half_T<<<(GDIM * EDIM) / 256, 256>>>(Wi);

    dim3 gridA(GDIM / 128, (S_LEN * BATCH) / 128);   // bn fastest -> x shared in L2
    xg_gemm_fp16<<<gridA, 256, smemA>>>(bi, bh);
    lstm_rec<<<BATCH, 256, smemR>>>(Wh, Wc, bc, out);
}